// round 7
// baseline (speedup 1.0000x reference)
#include <cuda_runtime.h>
#include <math.h>

#define NV 50257
#define NE 256
#define NC 48
#define NB 64
#define NT 1024
#define HT 512

#define LOG48    3.8712010109078911f
#define T1_LOG48 3960.2386341588226f   /* 1023 * log(48) */

// packed f32x2 helpers (Blackwell: fma.rn.f32x2 / add.rn.f32x2, 64-bit regs)
#define FMA2(acc, a, b) asm("fma.rn.f32x2 %0, %1, %2, %0;" : "+l"(acc) : "l"(a), "l"(b))
#define ADD2(a, b)      asm("add.rn.f32x2 %0, %0, %1;"     : "+l"(a)   : "l"(b))
__device__ __forceinline__ unsigned long long pack2(float lo, float hi) {
    unsigned long long r;
    asm("mov.b64 %0, {%1, %2};" : "=l"(r) : "r"(__float_as_uint(lo)), "r"(__float_as_uint(hi)));
    return r;
}
__device__ __forceinline__ unsigned long long bcast2(float v) {
    unsigned long long r;
    asm("mov.b64 %0, {%1, %1};" : "=l"(r) : "r"(__float_as_uint(v)));
    return r;
}
__device__ __forceinline__ float hadd2(unsigned long long a) {
    unsigned lo, hi;
    asm("mov.b64 {%0, %1}, %2;" : "=r"(lo), "=r"(hi) : "l"(a));
    return __uint_as_float(lo) + __uint_as_float(hi);
}
__device__ __forceinline__ float2 unpk2(unsigned long long a) {
    unsigned lo, hi;
    asm("mov.b64 {%0, %1}, %2;" : "=r"(lo), "=r"(hi) : "l"(a));
    return make_float2(__uint_as_float(lo), __uint_as_float(hi));
}

// Scratch (static device globals — no runtime allocation)
__device__ float g_P[NV * NC];        // emb_table @ fc_w^T + fc_b  (9.65 MB)
__device__ float g_ab[2][NB][NC];     // [0]=alpha_mid (fwd), [1]=beta_mid (bwd)
__device__ float g_num[2 * NB];       // per-block partial numerator
__device__ unsigned g_ctr;            // crf2 completion counter (reset by last block)

// ---------------------------------------------------------------------------
// K1: P[v, c] = sum_e emb[v, e] * fcw[c, e] + fcb[c]
// 256 threads, 128 rows/block; packed f32x2 FMA; W k-major in 48 KB smem.
// ---------------------------------------------------------------------------
__global__ __launch_bounds__(256)
void k_gemm(const float* __restrict__ emb, const float* __restrict__ fcw,
            const float* __restrict__ fcb) {
    __shared__ __align__(16) float Ws[NE * NC];   // 48 KB, k-major
    const int tid = threadIdx.x;
    const int m0 = blockIdx.x * 128;

    for (int idx = tid; idx < NC * NE; idx += 256) {
        int c = idx >> 8, k = idx & 255;
        Ws[k * NC + c] = fcw[idx];
    }
    __syncthreads();

    const int i = tid >> 2;
    const int q = tid & 3;
    const int row0 = m0 + i;
    const int row1 = m0 + 64 + i;
    const bool v0 = row0 < NV, v1 = row1 < NV;
    const float4* A0 = (const float4*)emb + (size_t)(v0 ? row0 : NV - 1) * 64;
    const float4* A1 = (const float4*)emb + (size_t)(v1 ? row1 : NV - 1) * 64;
    const unsigned long long* Wq = (const unsigned long long*)Ws + q * 6;

    unsigned long long c0[6], c1[6];
#pragma unroll
    for (int j = 0; j < 6; j++) { c0[j] = 0ull; c1[j] = 0ull; }

#pragma unroll 2
    for (int k4 = 0; k4 < 64; k4++) {
        float4 a0 = A0[k4];
        float4 a1 = A1[k4];
#pragma unroll
        for (int kk = 0; kk < 4; kk++) {
            float av0 = (kk == 0) ? a0.x : (kk == 1) ? a0.y : (kk == 2) ? a0.z : a0.w;
            float av1 = (kk == 0) ? a1.x : (kk == 1) ? a1.y : (kk == 2) ? a1.z : a1.w;
            unsigned long long pa0 = bcast2(av0);
            unsigned long long pa1 = bcast2(av1);
            const unsigned long long* wk = Wq + (size_t)(k4 * 4 + kk) * 24;
            ulonglong2 wA = *(const ulonglong2*)(wk + 0);
            ulonglong2 wB = *(const ulonglong2*)(wk + 2);
            ulonglong2 wC = *(const ulonglong2*)(wk + 4);
            FMA2(c0[0], pa0, wA.x); FMA2(c0[1], pa0, wA.y);
            FMA2(c0[2], pa0, wB.x); FMA2(c0[3], pa0, wB.y);
            FMA2(c0[4], pa0, wC.x); FMA2(c0[5], pa0, wC.y);
            FMA2(c1[0], pa1, wA.x); FMA2(c1[1], pa1, wA.y);
            FMA2(c1[2], pa1, wB.x); FMA2(c1[3], pa1, wB.y);
            FMA2(c1[4], pa1, wC.x); FMA2(c1[5], pa1, wC.y);
        }
    }

    float bias[12];
#pragma unroll
    for (int j = 0; j < 12; j++) bias[j] = fcb[q * 12 + j];

    if (v0) {
        float r[12];
#pragma unroll
        for (int j = 0; j < 6; j++) {
            float2 u = unpk2(c0[j]);
            r[2 * j] = u.x + bias[2 * j];
            r[2 * j + 1] = u.y + bias[2 * j + 1];
        }
        float4* o = (float4*)(g_P + (size_t)row0 * NC + q * 12);
        o[0] = make_float4(r[0], r[1], r[2], r[3]);
        o[1] = make_float4(r[4], r[5], r[6], r[7]);
        o[2] = make_float4(r[8], r[9], r[10], r[11]);
    }
    if (v1) {
        float r[12];
#pragma unroll
        for (int j = 0; j < 6; j++) {
            float2 u = unpk2(c1[j]);
            r[2 * j] = u.x + bias[2 * j];
            r[2 * j + 1] = u.y + bias[2 * j + 1];
        }
        float4* o = (float4*)(g_P + (size_t)row1 * NC + q * 12);
        o[0] = make_float4(r[0], r[1], r[2], r[3]);
        o[1] = make_float4(r[4], r[5], r[6], r[7]);
        o[2] = make_float4(r[8], r[9], r[10], r[11]);
    }
}

// packed 48-dot: sum_c p[c]*w[c]; p = 12 x ulonglong2 (16B-aligned smem),
// w = 24 packed u64 where wp[m] holds classes (2m, 2m+1). 24 FMA2, 6 chains.
__device__ __forceinline__ float dot48(const float* p, const unsigned long long* wp) {
    const ulonglong2* p2 = (const ulonglong2*)p;
    unsigned long long a0 = 0ull, a1 = 0ull, a2 = 0ull,
                       a3 = 0ull, a4 = 0ull, a5 = 0ull;
#pragma unroll
    for (int j = 0; j < 12; j += 3) {
        ulonglong2 v0 = p2[j], v1 = p2[j + 1], v2 = p2[j + 2];
        FMA2(a0, v0.x, wp[2 * j + 0]); FMA2(a1, v0.y, wp[2 * j + 1]);
        FMA2(a2, v1.x, wp[2 * j + 2]); FMA2(a3, v1.y, wp[2 * j + 3]);
        FMA2(a4, v2.x, wp[2 * j + 4]); FMA2(a5, v2.y, wp[2 * j + 5]);
    }
    ADD2(a0, a3); ADD2(a1, a4); ADD2(a2, a5);
    ADD2(a0, a1); ADD2(a0, a2);
    return hadd2(a0);
}

// ---------------------------------------------------------------------------
// K2: fused forward/backward CRF scan. The serial loop carries NO global
// stores — logits are materialized in a bulk float4 copy phase after the
// scan (MLP-rich, latency-hidden). Last block combines the loss.
// ---------------------------------------------------------------------------
__global__ __launch_bounds__(64, 1)
void k_crf2(const int* __restrict__ x, const int* __restrict__ lab,
            const float* __restrict__ st, const float* __restrict__ en,
            const float* __restrict__ tr, float* __restrict__ logits,
            float* __restrict__ loss_out) {
    __shared__ __align__(16) float pbuf[2][NC];
    __shared__ int xs[HT];
    const int tid = threadIdx.x;
    const int dir = blockIdx.x & 1;
    const int b   = blockIdx.x >> 1;
    const int base = b * NT;
    float* lg = logits + (size_t)base * NC;
    const float4* P4 = (const float4*)g_P;
    float4* lg4 = (float4*)lg;

    for (int s = tid; s < HT; s += 64) {
        int tok = dir ? (NT - 1 - s) : s;
        xs[s] = x[base + tok];
    }

    unsigned long long wp[24];   // wp[m] = classes (2m, 2m+1) of this thread's W line
    float boundary = 0.f;
#pragma unroll
    for (int m = 0; m < 24; m++) wp[m] = 0ull;
    if (tid < NC) {
        if (dir == 0) {   // fwd: owns column tid; sum over rows c
#pragma unroll 4
            for (int m = 0; m < 24; m++)
                wp[m] = pack2(__expf(tr[(2 * m) * NC + tid] - LOG48),
                              __expf(tr[(2 * m + 1) * NC + tid] - LOG48));
            boundary = st[tid];
        } else {          // bwd: owns row tid; sum over cols c
#pragma unroll 4
            for (int m = 0; m < 24; m++)
                wp[m] = pack2(__expf(tr[tid * NC + 2 * m] - LOG48),
                              __expf(tr[tid * NC + 2 * m + 1] - LOG48));
            boundary = en[tid];
        }
    }
    __syncthreads();   // xs ready

    float rv0 = 0.f, rv1 = 0.f, rv2 = 0.f;
    if (tid < NC) {
        rv0 = g_P[xs[0] * NC + tid];
        rv1 = g_P[xs[1] * NC + tid];
        rv2 = g_P[xs[2] * NC + tid];
    }
    int cur = 0;
    if (tid < NC) pbuf[0][tid] = __expf(rv0 + boundary);
    rv0 = rv1; rv1 = rv2;
    if (tid < NC) rv2 = g_P[xs[3] * NC + tid];
    __syncthreads();

    for (int s = 1; s < HT; s++) {
        float eraw = rv0;
        rv0 = rv1; rv1 = rv2;
        int sp = s + 3; if (sp > HT - 1) sp = HT - 1;
        int rowp = xs[sp];
        float e = __expf(eraw);           // MUFU early (lat 16), off critical path
        if (tid < NC) rv2 = g_P[rowp * NC + tid];

        float pn = dot48(pbuf[cur], wp) * e;
        if (tid < NC) pbuf[cur ^ 1][tid] = pn;
        cur ^= 1;
        __syncthreads();
    }

    float outv;
    if (dir == 1) outv = dot48(pbuf[cur], wp);   // beta_mid = (W g_511)/48
    else          outv = (tid < NC) ? pbuf[cur][tid] : 0.f;
    if (tid < NC) g_ab[dir][b][tid] = outv;

    // ---- bulk logits materialization: 512 rows of P -> logits, float4 ----
    for (int idx = tid; idx < HT * 12; idx += 64) {
        int s = idx / 12;
        int j = idx - s * 12;
        int tok = dir ? (NT - 1 - s) : s;
        lg4[tok * 12 + j] = P4[(size_t)xs[s] * 12 + j];
    }

    // ---- numerator half ----
    float np = 0.f;
    for (int s = tid; s < HT; s += 64) {
        int t = dir ? (HT + s) : s;
        int l = lab[base + t];
        np += g_P[x[base + t] * NC + l];
        int tp = dir ? (511 + s) : s;
        if (dir || tp < 511)
            np += tr[lab[base + tp] * NC + lab[base + tp + 1]];
    }
    if (tid == 0) np += dir ? en[lab[base + NT - 1]] : st[lab[base]];

#pragma unroll
    for (int o = 16; o; o >>= 1) np += __shfl_down_sync(0xffffffffu, np, o);
    __shared__ float rn[2];
    __shared__ unsigned rank;
    if ((tid & 31) == 0) rn[tid >> 5] = np;
    __syncthreads();
    if (tid == 0) {
        g_num[blockIdx.x] = rn[0] + rn[1];
        __threadfence();
        rank = atomicAdd(&g_ctr, 1u);
    }
    __syncthreads();

    if (rank == 2 * NB - 1) {            // last block combines
        __threadfence();
        int bb = tid;
        float dot = 0.f;
#pragma unroll 8
        for (int c = 0; c < NC; c++) dot += g_ab[0][bb][c] * g_ab[1][bb][c];
        float llh = g_num[2 * bb] + g_num[2 * bb + 1] - (logf(dot) + T1_LOG48);
        float v = llh;
#pragma unroll
        for (int o = 16; o; o >>= 1) v += __shfl_down_sync(0xffffffffu, v, o);
        __shared__ float rr[2];
        if ((tid & 31) == 0) rr[tid >> 5] = v;
        __syncthreads();
        if (tid == 0) {
            loss_out[0] = -(rr[0] + rr[1]);
            g_ctr = 0u;                  // reset for next graph replay
        }
    }
}

// ---------------------------------------------------------------------------
extern "C" void kernel_launch(void* const* d_in, const int* in_sizes, int n_in,
                              void* d_out, int out_size) {
    const int*   x    = (const int*)d_in[0];
    const int*   lab  = (const int*)d_in[1];
    const float* emb  = (const float*)d_in[2];
    const float* fcw  = (const float*)d_in[3];
    const float* fcb  = (const float*)d_in[4];
    const float* strt = (const float*)d_in[5];
    const float* endt = (const float*)d_in[6];
    const float* trns = (const float*)d_in[7];
    float* out = (float*)d_out;

    k_gemm<<<(NV + 127) / 128, 256>>>(emb, fcw, fcb);
    k_crf2<<<2 * NB, 64>>>(x, lab, strt, endt, trns, out, out + (out_size - 1));
}

// round 8
// speedup vs baseline: 1.3989x; 1.3989x over previous
#include <cuda_runtime.h>
#include <math.h>

#define NV 50257
#define NE 256
#define NC 48
#define NB 64
#define NT 1024
#define HT 512

#define LOG48    3.8712010109078911f
#define T1_LOG48 3960.2386341588226f   /* 1023 * log(48) */

// packed f32x2 helpers (Blackwell: fma.rn.f32x2 / add.rn.f32x2, 64-bit regs)
#define FMA2(acc, a, b) asm("fma.rn.f32x2 %0, %1, %2, %0;" : "+l"(acc) : "l"(a), "l"(b))
#define ADD2(a, b)      asm("add.rn.f32x2 %0, %0, %1;"     : "+l"(a)   : "l"(b))
__device__ __forceinline__ unsigned long long pack2(float lo, float hi) {
    unsigned long long r;
    asm("mov.b64 %0, {%1, %2};" : "=l"(r) : "r"(__float_as_uint(lo)), "r"(__float_as_uint(hi)));
    return r;
}
__device__ __forceinline__ unsigned long long bcast2(float v) {
    unsigned long long r;
    asm("mov.b64 %0, {%1, %1};" : "=l"(r) : "r"(__float_as_uint(v)));
    return r;
}
__device__ __forceinline__ float hadd2(unsigned long long a) {
    unsigned lo, hi;
    asm("mov.b64 {%0, %1}, %2;" : "=r"(lo), "=r"(hi) : "l"(a));
    return __uint_as_float(lo) + __uint_as_float(hi);
}
__device__ __forceinline__ float2 unpk2(unsigned long long a) {
    unsigned lo, hi;
    asm("mov.b64 {%0, %1}, %2;" : "=r"(lo), "=r"(hi) : "l"(a));
    return make_float2(__uint_as_float(lo), __uint_as_float(hi));
}

// Scratch (static device globals — no runtime allocation)
__device__ float g_P[NV * NC];        // emb_table @ fc_w^T + fc_b  (9.65 MB)
__device__ float g_ab[2][NB][NC];     // [0]=alpha_mid (fwd), [1]=beta_mid (bwd)
__device__ float g_num[2 * NB];       // per-block partial numerator
__device__ unsigned g_ctr;            // crf2 completion counter (reset by last block)

// ---------------------------------------------------------------------------
// K1: P[v, c] = sum_e emb[v, e] * fcw[c, e] + fcb[c]
// 256 threads, 128 rows/block; packed f32x2 FMA; W k-major in 48 KB smem.
// (unchanged — measured ~25 µs, on prediction)
// ---------------------------------------------------------------------------
__global__ __launch_bounds__(256)
void k_gemm(const float* __restrict__ emb, const float* __restrict__ fcw,
            const float* __restrict__ fcb) {
    __shared__ __align__(16) float Ws[NE * NC];   // 48 KB, k-major
    const int tid = threadIdx.x;
    const int m0 = blockIdx.x * 128;

    for (int idx = tid; idx < NC * NE; idx += 256) {
        int c = idx >> 8, k = idx & 255;
        Ws[k * NC + c] = fcw[idx];
    }
    __syncthreads();

    const int i = tid >> 2;
    const int q = tid & 3;
    const int row0 = m0 + i;
    const int row1 = m0 + 64 + i;
    const bool v0 = row0 < NV, v1 = row1 < NV;
    const float4* A0 = (const float4*)emb + (size_t)(v0 ? row0 : NV - 1) * 64;
    const float4* A1 = (const float4*)emb + (size_t)(v1 ? row1 : NV - 1) * 64;
    const unsigned long long* Wq = (const unsigned long long*)Ws + q * 6;

    unsigned long long c0[6], c1[6];
#pragma unroll
    for (int j = 0; j < 6; j++) { c0[j] = 0ull; c1[j] = 0ull; }

#pragma unroll 2
    for (int k4 = 0; k4 < 64; k4++) {
        float4 a0 = A0[k4];
        float4 a1 = A1[k4];
#pragma unroll
        for (int kk = 0; kk < 4; kk++) {
            float av0 = (kk == 0) ? a0.x : (kk == 1) ? a0.y : (kk == 2) ? a0.z : a0.w;
            float av1 = (kk == 0) ? a1.x : (kk == 1) ? a1.y : (kk == 2) ? a1.z : a1.w;
            unsigned long long pa0 = bcast2(av0);
            unsigned long long pa1 = bcast2(av1);
            const unsigned long long* wk = Wq + (size_t)(k4 * 4 + kk) * 24;
            ulonglong2 wA = *(const ulonglong2*)(wk + 0);
            ulonglong2 wB = *(const ulonglong2*)(wk + 2);
            ulonglong2 wC = *(const ulonglong2*)(wk + 4);
            FMA2(c0[0], pa0, wA.x); FMA2(c0[1], pa0, wA.y);
            FMA2(c0[2], pa0, wB.x); FMA2(c0[3], pa0, wB.y);
            FMA2(c0[4], pa0, wC.x); FMA2(c0[5], pa0, wC.y);
            FMA2(c1[0], pa1, wA.x); FMA2(c1[1], pa1, wA.y);
            FMA2(c1[2], pa1, wB.x); FMA2(c1[3], pa1, wB.y);
            FMA2(c1[4], pa1, wC.x); FMA2(c1[5], pa1, wC.y);
        }
    }

    float bias[12];
#pragma unroll
    for (int j = 0; j < 12; j++) bias[j] = fcb[q * 12 + j];

    if (v0) {
        float r[12];
#pragma unroll
        for (int j = 0; j < 6; j++) {
            float2 u = unpk2(c0[j]);
            r[2 * j] = u.x + bias[2 * j];
            r[2 * j + 1] = u.y + bias[2 * j + 1];
        }
        float4* o = (float4*)(g_P + (size_t)row0 * NC + q * 12);
        o[0] = make_float4(r[0], r[1], r[2], r[3]);
        o[1] = make_float4(r[4], r[5], r[6], r[7]);
        o[2] = make_float4(r[8], r[9], r[10], r[11]);
    }
    if (v1) {
        float r[12];
#pragma unroll
        for (int j = 0; j < 6; j++) {
            float2 u = unpk2(c1[j]);
            r[2 * j] = u.x + bias[2 * j];
            r[2 * j + 1] = u.y + bias[2 * j + 1];
        }
        float4* o = (float4*)(g_P + (size_t)row1 * NC + q * 12);
        o[0] = make_float4(r[0], r[1], r[2], r[3]);
        o[1] = make_float4(r[4], r[5], r[6], r[7]);
        o[2] = make_float4(r[8], r[9], r[10], r[11]);
    }
}

// packed 48-dot: sum_c p[c]*w[c]; p = 12 x ulonglong2 (16B-aligned smem),
// w = 24 packed u64 where wp[m] holds classes (2m, 2m+1). 24 FMA2, 6 chains.
__device__ __forceinline__ float dot48(const float* p, const unsigned long long* wp) {
    const ulonglong2* p2 = (const ulonglong2*)p;
    unsigned long long a0 = 0ull, a1 = 0ull, a2 = 0ull,
                       a3 = 0ull, a4 = 0ull, a5 = 0ull;
#pragma unroll
    for (int j = 0; j < 12; j += 3) {
        ulonglong2 v0 = p2[j], v1 = p2[j + 1], v2 = p2[j + 2];
        FMA2(a0, v0.x, wp[2 * j + 0]); FMA2(a1, v0.y, wp[2 * j + 1]);
        FMA2(a2, v1.x, wp[2 * j + 2]); FMA2(a3, v1.y, wp[2 * j + 3]);
        FMA2(a4, v2.x, wp[2 * j + 4]); FMA2(a5, v2.y, wp[2 * j + 5]);
    }
    ADD2(a0, a3); ADD2(a1, a4); ADD2(a2, a5);
    ADD2(a0, a1); ADD2(a0, a2);
    return hadd2(a0);
}

// ---------------------------------------------------------------------------
// K2: fused forward/backward CRF scan, smem-staged emissions.
// Phase 1: bulk float4 gather of this block's 512 emission rows from g_P
//          into dynamic smem AND into the logits output (fused).
// Phase 2: serial scan with NO global memory access — LDS only.
// Phase 3: numerator (emissions from smem) + last-block loss combine.
// Dynamic smem: pbuf[2][48] | es[512*48] | xs[512]  (~101 KB, 1 block/SM).
// ---------------------------------------------------------------------------
__global__ __launch_bounds__(64, 1)
void k_crf2(const int* __restrict__ x, const int* __restrict__ lab,
            const float* __restrict__ st, const float* __restrict__ en,
            const float* __restrict__ tr, float* __restrict__ logits,
            float* __restrict__ loss_out) {
    extern __shared__ __align__(16) float sm[];
    float* pbuf0 = sm;                 // [2][NC]
    float* pbuf1 = sm + NC;
    float* es    = sm + 2 * NC;        // [HT][NC] raw emissions (16B-aligned: 384B offset)
    int*   xs    = (int*)(es + HT * NC);

    const int tid = threadIdx.x;
    const int dir = blockIdx.x & 1;
    const int b   = blockIdx.x >> 1;
    const int base = b * NT;
    const int ci = (tid < NC) ? tid : 0;       // clamped class index
    float4* lg4 = (float4*)(logits + (size_t)base * NC);
    const float4* P4 = (const float4*)g_P;

    for (int s = tid; s < HT; s += 64) {
        int tok = dir ? (NT - 1 - s) : s;
        xs[s] = x[base + tok];
    }

    unsigned long long wp[24];   // wp[m] = classes (2m, 2m+1) of this thread's W line
    float boundary = 0.f;
#pragma unroll
    for (int m = 0; m < 24; m++) wp[m] = 0ull;
    if (tid < NC) {
        if (dir == 0) {   // fwd: owns column tid; sum over rows c
#pragma unroll 4
            for (int m = 0; m < 24; m++)
                wp[m] = pack2(__expf(tr[(2 * m) * NC + tid] - LOG48),
                              __expf(tr[(2 * m + 1) * NC + tid] - LOG48));
            boundary = st[tid];
        } else {          // bwd: owns row tid; sum over cols c
#pragma unroll 4
            for (int m = 0; m < 24; m++)
                wp[m] = pack2(__expf(tr[tid * NC + 2 * m] - LOG48),
                              __expf(tr[tid * NC + 2 * m + 1] - LOG48));
            boundary = en[tid];
        }
    }
    __syncthreads();   // xs ready

    // ---- Phase 1: bulk emission stage (g_P -> smem) + logits write (fused) --
    {
        float4* es4 = (float4*)es;
#pragma unroll 4
        for (int idx = tid; idx < HT * 12; idx += 64) {
            int s = idx / 12;
            int j = idx - s * 12;
            float4 v = P4[(size_t)xs[s] * 12 + j];
            es4[idx] = v;
            int tok = dir ? (NT - 1 - s) : s;
            lg4[tok * 12 + j] = v;
        }
    }
    __syncthreads();   // es ready

    // ---- Phase 2: serial scan (LDS-only loop) ----
    float* pb[2] = {pbuf0, pbuf1};
    if (tid < NC) pbuf0[tid] = __expf(es[ci] + boundary);
    __syncthreads();

    int cur = 0;
    for (int s = 1; s < HT; s++) {
        float eraw = es[s * NC + ci];      // LDS, off critical path
        float e = __expf(eraw);            // MUFU lat 16, off critical path
        float pn = dot48(pb[cur], wp) * e;
        if (tid < NC) pb[cur ^ 1][tid] = pn;
        cur ^= 1;
        __syncthreads();
    }

    float outv;
    if (dir == 1) outv = dot48(pb[cur], wp);   // beta_mid = (W g_511)/48
    else          outv = (tid < NC) ? pb[cur][tid] : 0.f;
    if (tid < NC) g_ab[dir][b][tid] = outv;

    // ---- Phase 3: numerator half (emissions via smem) ----
    float np = 0.f;
    for (int s = tid; s < HT; s += 64) {
        int t = dir ? (HT + s) : s;
        int es_idx = dir ? (511 - s) : s;      // es row holding emissions of token t
        np += es[es_idx * NC + lab[base + t]];
        int tp = dir ? (511 + s) : s;
        if (dir || tp < 511)
            np += tr[lab[base + tp] * NC + lab[base + tp + 1]];
    }
    if (tid == 0) np += dir ? en[lab[base + NT - 1]] : st[lab[base]];

#pragma unroll
    for (int o = 16; o; o >>= 1) np += __shfl_down_sync(0xffffffffu, np, o);
    __shared__ float rn[2];
    __shared__ unsigned rank;
    if ((tid & 31) == 0) rn[tid >> 5] = np;
    __syncthreads();
    if (tid == 0) {
        g_num[blockIdx.x] = rn[0] + rn[1];
        __threadfence();
        rank = atomicAdd(&g_ctr, 1u);
    }
    __syncthreads();

    if (rank == 2 * NB - 1) {            // last block combines
        __threadfence();
        int bb = tid;
        float dot = 0.f;
#pragma unroll 8
        for (int c = 0; c < NC; c++) dot += g_ab[0][bb][c] * g_ab[1][bb][c];
        float llh = g_num[2 * bb] + g_num[2 * bb + 1] - (logf(dot) + T1_LOG48);
        float v = llh;
#pragma unroll
        for (int o = 16; o; o >>= 1) v += __shfl_down_sync(0xffffffffu, v, o);
        __shared__ float rr[2];
        if ((tid & 31) == 0) rr[tid >> 5] = v;
        __syncthreads();
        if (tid == 0) {
            loss_out[0] = -(rr[0] + rr[1]);
            g_ctr = 0u;                  // reset for next graph replay
        }
    }
}

// ---------------------------------------------------------------------------
extern "C" void kernel_launch(void* const* d_in, const int* in_sizes, int n_in,
                              void* d_out, int out_size) {
    const int*   x    = (const int*)d_in[0];
    const int*   lab  = (const int*)d_in[1];
    const float* emb  = (const float*)d_in[2];
    const float* fcw  = (const float*)d_in[3];
    const float* fcb  = (const float*)d_in[4];
    const float* strt = (const float*)d_in[5];
    const float* endt = (const float*)d_in[6];
    const float* trns = (const float*)d_in[7];
    float* out = (float*)d_out;

    size_t smem = (size_t)(2 * NC + HT * NC) * sizeof(float) + HT * sizeof(int);
    static int smem_set = 0;
    if (!smem_set) {   // host-side attribute set (not graph-captured work)
        cudaFuncSetAttribute(k_crf2, cudaFuncAttributeMaxDynamicSharedMemorySize,
                             (int)smem);
        smem_set = 1;
    }

    k_gemm<<<(NV + 127) / 128, 256>>>(emb, fcw, fcb);
    k_crf2<<<2 * NB, 64, smem>>>(x, lab, strt, endt, trns, out, out + (out_size - 1));
}